// round 16
// baseline (speedup 1.0000x reference)
#include <cuda_runtime.h>
#include <cuda_fp16.h>

#define IMG      384
#define W_OUT    48          // 8 * 48 = 384 exact
#define LCOLS    60          // 48 + 6+6 halo
#define TILE_H   24          // output rows per block: grid 4096 = 6.92 waves (tail 92%)
#define NLOAD    (TILE_H + 12)  // 36 input rows per column
#define ROW_U2   (LCOLS * 4) // uint2 (half4) per smem row = 240 -> 1920 B
#define SMEM_BYTES (TILE_H * ROW_U2 * 8)   // 46080 B -> 4 blocks/SM = 180 KB

// Normalized 1D gaussian, sigma=2, ws=13 (literals -> imm-form FMA)
__device__ constexpr float GW[13] = {
    0.0022181959f, 0.0087731350f, 0.0270231560f, 0.0648251852f,
    0.1211093910f, 0.1762131227f, 0.1996756275f, 0.1762131227f,
    0.1211093910f, 0.0648251852f, 0.0270231560f, 0.0087731350f,
    0.0022181959f };

__device__ __forceinline__ float4 f4z() { return make_float4(0.f, 0.f, 0.f, 0.f); }

union H2U { __half2 h; unsigned u; };

// pack float4 -> 2x half2
__device__ __forceinline__ uint2 pack_h4(float4 v) {
    H2U a, b;
    a.h = __floats2half2_rn(v.x, v.y);
    b.h = __floats2half2_rn(v.z, v.w);
    uint2 r; r.x = a.u; r.y = b.u;
    return r;
}

__global__ __launch_bounds__(256, 4)
void gauss13_kernel(const float* __restrict__ in, float* __restrict__ out)
{
    // smem: [TILE_H rows][60 pixels][4 quads] of half4 (8 B). Full 16-ch pixel = 32 B.
    extern __shared__ uint2 sV[];

    const int n  = blockIdx.z;           // batch (full 16 channels per block)
    const int x0 = blockIdx.x * W_OUT;
    const int y0 = blockIdx.y * TILE_H;
    const int tid = threadIdx.x;

    const float4* __restrict__ ibase =
        reinterpret_cast<const float4*>(in) + (size_t)n * (IMG * IMG * 4);
    float4* __restrict__ obase =
        reinterpret_cast<float4*>(out) + (size_t)n * (IMG * IMG * 4);

    // ---- vertical pass: 16-slot packed ring, prefetch stage, HFMA2 dual-tree ----
    {
        const int q   = tid & 3;
        const int col = tid >> 2;          // 0..63; only 0..59 active
        if (col < LCOLS) {
            const int gw  = x0 - 6 + col;
            const bool wok = ((unsigned)gw < (unsigned)IMG);
            const int r0  = y0 - 6;
            const float4* cb = ibase + q;
            uint2* sp = sV + col * 4 + q;

            auto ldrow = [&](int i) -> float4 {
                const int h = r0 + i;
                return (wok && (unsigned)h < (unsigned)IMG)
                     ? __ldg(cb + ((size_t)h * IMG + gw) * 4) : f4z();
            };

            uint2 win[16];                 // packed half4 ring (32 regs)
            #pragma unroll
            for (int i = 0; i < 14; ++i)
                win[i] = pack_h4(ldrow(i));
            float4 pf = ldrow(14);         // staged raw row

            #pragma unroll
            for (int r = 0; r < TILE_H; ++r) {
                win[(r + 14) & 15] = pack_h4(pf);
                if (r + 15 < NLOAD)
                    pf = ldrow(r + 15);

                H2U sA0, sA1, sB0, sB1;
                sA0.h = __float2half2_rn(0.f); sA1.h = __float2half2_rn(0.f);
                sB0.h = __float2half2_rn(0.f); sB1.h = __float2half2_rn(0.f);
                #pragma unroll
                for (int k = 0; k < 7; ++k) {
                    const uint2 w = win[(r + k) & 15];
                    const __half2 wk2 = __float2half2_rn(GW[k]);
                    H2U v0, v1; v0.u = w.x; v1.u = w.y;
                    sA0.h = __hfma2(wk2, v0.h, sA0.h);
                    sA1.h = __hfma2(wk2, v1.h, sA1.h);
                }
                #pragma unroll
                for (int k = 7; k < 13; ++k) {
                    const uint2 w = win[(r + k) & 15];
                    const __half2 wk2 = __float2half2_rn(GW[k]);
                    H2U v0, v1; v0.u = w.x; v1.u = w.y;
                    sB0.h = __hfma2(wk2, v0.h, sB0.h);
                    sB1.h = __hfma2(wk2, v1.h, sB1.h);
                }
                H2U a01, a23;
                a01.h = __hadd2(sA0.h, sB0.h);
                a23.h = __hadd2(sA1.h, sB1.h);
                uint2 pk; pk.x = a01.u; pk.y = a23.u;
                sp[r * ROW_U2] = pk;       // 128 B contiguous per 16-lane phase
            }
        }
    }
    __syncthreads();

    // ---- horizontal pass: 384 (q,seg,row) jobs on 256 threads (job loop, no unroll) ----
    {
        #pragma unroll 1
        for (int job = tid; job < 16 * TILE_H; job += 256) {
            const int q   = job & 3;
            const int seg = (job >> 2) & 3;    // output col = seg + 4*i
            const int row = job >> 4;          // 0..23

            float4 acc[12];
            #pragma unroll
            for (int i = 0; i < 12; ++i) acc[i] = f4z();

            const uint2* rowp = sV + row * ROW_U2 + q;

            #pragma unroll
            for (int c = 0; c < 57; ++c) {     // c in [4i, 4i+12] for i = 0..11
                uint2 pk = rowp[(seg + c) * 4];
                H2U u0, u1; u0.u = pk.x; u1.u = pk.y;
                float2 f01 = __half22float2(u0.h);
                float2 f23 = __half22float2(u1.h);
                #pragma unroll
                for (int i = 0; i < 12; ++i) {
                    const int k = c - 4 * i;
                    if (k >= 0 && k < 13) {     // compile-time pruned
                        const float wk = GW[k]; // literal -> FFMA-imm
                        acc[i].x = fmaf(wk, f01.x, acc[i].x);
                        acc[i].y = fmaf(wk, f01.y, acc[i].y);
                        acc[i].z = fmaf(wk, f23.x, acc[i].z);
                        acc[i].w = fmaf(wk, f23.y, acc[i].w);
                    }
                }
            }

            const int gy = y0 + row;
            float4* ob = obase + q;
            #pragma unroll
            for (int i = 0; i < 12; ++i) {
                const int gx = x0 + seg + 4 * i;   // always < 384
                ob[((size_t)gy * IMG + gx) * 4] = acc[i];
            }
        }
    }
}

extern "C" void kernel_launch(void* const* d_in, const int* in_sizes, int n_in,
                              void* d_out, int out_size)
{
    (void)in_sizes; (void)n_in; (void)out_size;
    const float* x = (const float*)d_in[0];
    float* y = (float*)d_out;

    cudaFuncSetAttribute(gauss13_kernel,
                         cudaFuncAttributeMaxDynamicSharedMemorySize, SMEM_BYTES);

    dim3 grid(IMG / W_OUT /* 8 */, IMG / TILE_H /* 16 */, 32);
    dim3 block(256);
    gauss13_kernel<<<grid, block, SMEM_BYTES>>>(x, y);
}

// round 17
// speedup vs baseline: 1.1384x; 1.1384x over previous
#include <cuda_runtime.h>
#include <cuda_fp16.h>

#define IMG      384
#define W_OUT    48          // 8 * 48 = 384 exact
#define LCOLS    60          // 48 + 6+6 halo
#define TILE_H   16          // output rows per block
#define NLOAD    (TILE_H + 12)  // 28 input rows per column
#define ROW_U2   (LCOLS * 4) // uint2 (half4) per smem row = 240 -> 1920 B
#define SMEM_BYTES (TILE_H * ROW_U2 * 8)   // 30720 B -> 4 blocks/SM

// Normalized 1D gaussian, sigma=2, ws=13 (literals -> imm-form FMA)
__device__ constexpr float GW[13] = {
    0.0022181959f, 0.0087731350f, 0.0270231560f, 0.0648251852f,
    0.1211093910f, 0.1762131227f, 0.1996756275f, 0.1762131227f,
    0.1211093910f, 0.0648251852f, 0.0270231560f, 0.0087731350f,
    0.0022181959f };

__device__ __forceinline__ float4 f4z() { return make_float4(0.f, 0.f, 0.f, 0.f); }

union H2U { __half2 h; unsigned u; };

// pack float4 -> 2x half2
__device__ __forceinline__ uint2 pack_h4(float4 v) {
    H2U a, b;
    a.h = __floats2half2_rn(v.x, v.y);
    b.h = __floats2half2_rn(v.z, v.w);
    uint2 r; r.x = a.u; r.y = b.u;
    return r;
}

__global__ __launch_bounds__(256, 4)
void gauss13_kernel(const float* __restrict__ in, float* __restrict__ out)
{
    // smem: [TILE_H rows][60 pixels][4 quads] of half4 (8 B). Full 16-ch pixel = 32 B.
    extern __shared__ uint2 sV[];

    const int n  = blockIdx.z;           // batch (full 16 channels per block)
    const int x0 = blockIdx.x * W_OUT;
    const int y0 = blockIdx.y * TILE_H;
    const int tid = threadIdx.x;

    const float4* __restrict__ ibase =
        reinterpret_cast<const float4*>(in) + (size_t)n * (IMG * IMG * 4);
    float4* __restrict__ obase =
        reinterpret_cast<float4*>(out) + (size_t)n * (IMG * IMG * 4);

    // ---- vertical pass: 16-slot packed ring, DEPTH-2 prefetch, HFMA2 dual-tree ----
    {
        const int q   = tid & 3;
        const int col = tid >> 2;          // 0..63; only 0..59 active
        if (col < LCOLS) {
            const int gw  = x0 - 6 + col;
            const bool wok = ((unsigned)gw < (unsigned)IMG);
            const int r0  = y0 - 6;
            const float4* cb = ibase + q;
            uint2* sp = sV + col * 4 + q;

            auto ldrow = [&](int i) -> float4 {
                const int h = r0 + i;
                return (wok && (unsigned)h < (unsigned)IMG)
                     ? __ldg(cb + ((size_t)h * IMG + gw) * 4) : f4z();
            };

            uint2 win[16];                 // packed half4 ring (32 regs)
            #pragma unroll
            for (int i = 0; i < 14; ++i)
                win[i] = pack_h4(ldrow(i));
            float4 pf1 = ldrow(14);        // staged raw rows (2-deep pipeline)
            float4 pf2 = ldrow(15);

            #pragma unroll
            for (int r = 0; r < TILE_H; ++r) {
                // insert row r+14; rotate stages; issue LDG for row r+16
                win[(r + 14) & 15] = pack_h4(pf1);
                pf1 = pf2;
                if (r + 16 < NLOAD)
                    pf2 = ldrow(r + 16);

                // dual-tree tap accumulation (chain depth ~7)
                H2U sA0, sA1, sB0, sB1;
                sA0.h = __float2half2_rn(0.f); sA1.h = __float2half2_rn(0.f);
                sB0.h = __float2half2_rn(0.f); sB1.h = __float2half2_rn(0.f);
                #pragma unroll
                for (int k = 0; k < 7; ++k) {
                    const uint2 w = win[(r + k) & 15];
                    const __half2 wk2 = __float2half2_rn(GW[k]);
                    H2U v0, v1; v0.u = w.x; v1.u = w.y;
                    sA0.h = __hfma2(wk2, v0.h, sA0.h);
                    sA1.h = __hfma2(wk2, v1.h, sA1.h);
                }
                #pragma unroll
                for (int k = 7; k < 13; ++k) {
                    const uint2 w = win[(r + k) & 15];
                    const __half2 wk2 = __float2half2_rn(GW[k]);
                    H2U v0, v1; v0.u = w.x; v1.u = w.y;
                    sB0.h = __hfma2(wk2, v0.h, sB0.h);
                    sB1.h = __hfma2(wk2, v1.h, sB1.h);
                }
                H2U a01, a23;
                a01.h = __hadd2(sA0.h, sB0.h);
                a23.h = __hadd2(sA1.h, sB1.h);
                uint2 pk; pk.x = a01.u; pk.y = a23.u;
                sp[r * ROW_U2] = pk;       // 128 B contiguous per 16-lane phase
            }
        }
    }
    __syncthreads();

    // ------------- horizontal pass (smem fp16 -> f32 accum -> global) ----------------
    // thread = (q, seg, row): warp stores 4 consecutive full pixels x 2 rows.
    {
        const int q   = tid & 3;
        const int seg = (tid >> 2) & 3;
        const int row = tid >> 4;          // 0..15

        float4 acc[12];
        #pragma unroll
        for (int i = 0; i < 12; ++i) acc[i] = f4z();

        const uint2* rowp = sV + row * ROW_U2 + q;

        #pragma unroll
        for (int c = 0; c < 57; ++c) {     // c in [4i, 4i+12] for i = 0..11
            uint2 pk = rowp[(seg + c) * 4];
            H2U u0, u1; u0.u = pk.x; u1.u = pk.y;
            float2 f01 = __half22float2(u0.h);
            float2 f23 = __half22float2(u1.h);
            #pragma unroll
            for (int i = 0; i < 12; ++i) {
                const int k = c - 4 * i;
                if (k >= 0 && k < 13) {     // compile-time pruned
                    const float wk = GW[k]; // literal -> FFMA-imm
                    acc[i].x = fmaf(wk, f01.x, acc[i].x);
                    acc[i].y = fmaf(wk, f01.y, acc[i].y);
                    acc[i].z = fmaf(wk, f23.x, acc[i].z);
                    acc[i].w = fmaf(wk, f23.y, acc[i].w);
                }
            }
        }

        const int gy = y0 + row;
        float4* ob = obase + q;
        #pragma unroll
        for (int i = 0; i < 12; ++i) {
            const int gx = x0 + seg + 4 * i;   // always < 384
            ob[((size_t)gy * IMG + gx) * 4] = acc[i];
        }
    }
}

extern "C" void kernel_launch(void* const* d_in, const int* in_sizes, int n_in,
                              void* d_out, int out_size)
{
    (void)in_sizes; (void)n_in; (void)out_size;
    const float* x = (const float*)d_in[0];
    float* y = (float*)d_out;

    cudaFuncSetAttribute(gauss13_kernel,
                         cudaFuncAttributeMaxDynamicSharedMemorySize, SMEM_BYTES);

    dim3 grid(IMG / W_OUT /* 8 */, IMG / TILE_H /* 24 */, 32);
    dim3 block(256);
    gauss13_kernel<<<grid, block, SMEM_BYTES>>>(x, y);
}